// round 15
// baseline (speedup 1.0000x reference)
#include <cuda_runtime.h>
#include <cuda_fp16.h>
#include <math.h>
#include <stdint.h>

#define BATCH 16384
#define KC 64                       // K elements per SMEM stage
#define STAGE_BYTES 32768           // A 16KB + B 16KB
#define A_OFF 0
#define B_OFF 16384
#define NSTAGE 3
#define GEMM_SMEM (NSTAGE * STAGE_BYTES)
#define GTHREADS 256
// fused head kernel: CTA 128x256, A 16KB + B 32KB
#define HSTAGE_BYTES 49152
#define HGEMM_SMEM (NSTAGE * HSTAGE_BYTES)
#define HTHREADS 512

// ---------------- scratch (no allocations allowed) ----------------
__device__ __half g_h1[BATCH * 1024];
__device__ __half g_h2[BATCH * 1024];
__device__ __half g_a1[BATCH * 512];
// weights: fp16, transposed to K-major + pre-swizzled blocked tiles
// blocked layout: [c][nt=N/128][kt=K/64][8192 elems]
__device__ __half g_w1[256 * 1024];
__device__ __half g_w2[1024 * 1024];
__device__ __half g_hw1[4 * 1024 * 512];
__device__ __half g_hw2[4 * 512 * 256];
__device__ int g_rowmap[BATCH];
__device__ int g_off[5];

// ---------------- static streams/events for graph fork-join -------------------
struct _GraphStreams {
    cudaStream_t side;
    cudaEvent_t fork, join;
    _GraphStreams() {
        cudaStreamCreateWithFlags(&side, cudaStreamNonBlocking);
        cudaEventCreateWithFlags(&fork, cudaEventDisableTiming);
        cudaEventCreateWithFlags(&join, cudaEventDisableTiming);
    }
};
static _GraphStreams g_gs;

// ---------------- helpers (baseline PTX only) ----------------
__device__ __forceinline__ uint32_t smem_u32(const void* p) {
    uint32_t a;
    asm("{ .reg .u64 t; cvta.to.shared.u64 t, %1; cvt.u32.u64 %0, t; }" : "=r"(a) : "l"(p));
    return a;
}
#define LDSM_X4(r0, r1, r2, r3, addr) \
    asm volatile("ldmatrix.sync.aligned.m8n8.x4.shared.b16 {%0,%1,%2,%3}, [%4];" \
                 : "=r"(r0), "=r"(r1), "=r"(r2), "=r"(r3) : "r"(addr))
#define CP16(dst, src) \
    asm volatile("cp.async.cg.shared.global [%0], [%1], 16;" :: "r"(dst), "l"(src) : "memory")
#define CP_COMMIT() asm volatile("cp.async.commit_group;" ::: "memory")
#define CP_WAIT1() asm volatile("cp.async.wait_group 1;" ::: "memory")
#define CP_WAIT0() asm volatile("cp.async.wait_group 0;" ::: "memory")

__device__ __forceinline__ void mma_fp16(float* d, const uint32_t* a, uint32_t b0, uint32_t b1) {
    asm volatile(
        "mma.sync.aligned.m16n8k16.row.col.f32.f16.f16.f32 "
        "{%0,%1,%2,%3}, {%4,%5,%6,%7}, {%8,%9}, {%0,%1,%2,%3};"
        : "+f"(d[0]), "+f"(d[1]), "+f"(d[2]), "+f"(d[3])
        : "r"(a[0]), "r"(a[1]), "r"(a[2]), "r"(a[3]), "r"(b0), "r"(b1));
}
__device__ __forceinline__ uint32_t pack2h(__half a, __half b) {
    return ((uint32_t)__half_as_ushort(b) << 16) | (uint32_t)__half_as_ushort(a);
}
__device__ __forceinline__ uint32_t swz(uint32_t off) { return off ^ ((off >> 3) & 0x70); }

// ---------------- splitW worker: one 8-deep k-column of one weight matrix -----
__device__ __forceinline__ void splitW_item(const float* __restrict__ src, __half* __restrict__ dh,
                                            int K, int N, int idx) {
    const int kg = K >> 3;
    const int n_ = idx % N;
    const int t  = idx / N;
    const int k8 = (t % kg) * 8;
    const int c  = t / kg;

    const float* s = src + ((size_t)c * K + k8) * N + n_;
    __half hb[8];
    #pragma unroll
    for (int j = 0; j < 8; j++) hb[j] = __float2half_rn(s[(size_t)j * N]);

    const int nt = n_ >> 7, rr = n_ & 127, kt = k8 >> 6, kk = k8 & 63;
    const size_t base = (((size_t)c * (N >> 7) + nt) * (K >> 6) + kt) * 8192;
    const uint32_t sw = swz((uint32_t)rr * 128 + kk * 2);
    *(uint4*)((char*)(dh + base) + sw) = *(uint4*)hb;
}

// ---------------- main-stream prep: convert W1 only ---------------------------
__global__ void prep_main_k(const float* __restrict__ W1) {
    int idx = blockIdx.x * 1024 + threadIdx.x;
    if (idx < 32768) splitW_item(W1, g_w1, 256, 1024, idx);
}

// ---------------- side-stream prep: partition + HW1/HW2/W2 --------------------
// block 0: partition; blocks [1,449): HW1 (262144), HW2 (65536), W2 (131072)
__global__ void prep_side_k(const int* __restrict__ flags,
                            const float* __restrict__ HW1, const float* __restrict__ HW2,
                            const float* __restrict__ W2) {
    const int b = blockIdx.x;
    const int tid = threadIdx.x;
    if (b == 0) {
        __shared__ int soff[4];
        const int lane = tid & 31;
        if (tid < 4) soff[tid] = 0;
        __syncthreads();
        for (int i = tid; i < BATCH; i += 1024) {
            int c = flags[2 * i] * 2 + flags[2 * i + 1];
            unsigned same = __match_any_sync(0xFFFFFFFFu, c);
            int leader = __ffs(same) - 1;
            if (lane == leader) atomicAdd(&soff[c], __popc(same));
        }
        __syncthreads();
        if (tid == 0) {
            int o = 0;
            #pragma unroll
            for (int c = 0; c < 4; c++) { int n = soff[c]; g_off[c] = o; soff[c] = o; o += n; }
            g_off[4] = o;
        }
        __syncthreads();
        for (int i = tid; i < BATCH; i += 1024) {
            int c = flags[2 * i] * 2 + flags[2 * i + 1];
            unsigned same = __match_any_sync(0xFFFFFFFFu, c);
            int leader = __ffs(same) - 1;
            int rank = __popc(same & ((1u << lane) - 1u));
            int base = 0;
            if (lane == leader) base = atomicAdd(&soff[c], __popc(same));
            base = __shfl_sync(0xFFFFFFFFu, base, leader);
            g_rowmap[base + rank] = i;
        }
    } else {
        int widx = (b - 1) * 1024 + tid;
        if (widx < 262144)      splitW_item(HW1, g_hw1, 1024, 512, widx);
        else if (widx < 327680) splitW_item(HW2, g_hw2, 512, 256, widx - 262144);
        else if (widx < 458752) splitW_item(W2,  g_w2, 1024, 1024, widx - 327680);
    }
}

// ---------------- warp-MMA fp16 GEMM + bias + relu (256 thr, 2 CTA/SM) --------
// CTA tile 128x128, 8 warps in 4(m) x 2(n) grid, warp tile 32x64.
// MODE: 0 dense, 1 gather via g_rowmap
// ASRC: 0 fp32 x (inline convert), 1 g_h1, 2 g_h2
// WSRC: 0 w1, 1 w2, 2 hw1 / DST: 0 g_h1, 1 g_h2, 2 g_a1
template <int MODE, int ASRC, int WSRC, int DST, int K, int N>
__global__ __launch_bounds__(GTHREADS, 2)
void gemm_mma(const float* __restrict__ Bias, const float* __restrict__ Xsrc)
{
    extern __shared__ __align__(1024) char smem[];
    constexpr int NK = K / KC;
    const int tid = threadIdx.x;
    const int c = blockIdx.z;

    int mstart, mend;
    if (MODE == 0) { mstart = 0; mend = BATCH; }
    else           { mstart = g_off[c]; mend = g_off[c + 1]; }
    const int m0 = mstart + blockIdx.y * 128;
    if (m0 >= mend) return;
    const int n0 = blockIdx.x * 128;

    const float* bc = Bias + (size_t)c * N;
    const uint32_t smb = smem_u32(smem);

    const __half* Ab = (ASRC == 1) ? g_h1 : g_h2;
    const __half* Wb;
    if (WSRC == 0)      Wb = g_w1;
    else if (WSRC == 1) Wb = g_w2;
    else                Wb = g_hw1;
    const __half* Wt = Wb + (((size_t)c * (N >> 7) + blockIdx.x) * (K >> 6)) * 8192;

    const int ar = tid >> 1;
    const int aqe = (tid & 1) * 32;
    int apos = m0 + ar;
    if (apos > mend - 1) apos = mend - 1;
    const int grow = (MODE == 1) ? g_rowmap[apos] : apos;
    const __half* Ar = (ASRC == 0) ? nullptr : (Ab + (size_t)grow * K + aqe);
    const float* Axf = (ASRC == 0) ? (Xsrc + (size_t)grow * K + aqe) : nullptr;
    const uint32_t a_sw_base = (uint32_t)ar * 128 + aqe * 2;

    auto issue = [&](int kc) {
        const int s = kc % NSTAGE;
        const uint32_t stb = smb + s * STAGE_BYTES;
        char* stc = smem + s * STAGE_BYTES;
        const int k0 = kc * KC;
        if (ASRC == 0) {
            // fp32 x: LDG + convert + STS (gemm1 only)
            #pragma unroll
            for (int j = 0; j < 4; j++) {
                float4 v0 = *(const float4*)(Axf + k0 + j * 8);
                float4 v1 = *(const float4*)(Axf + k0 + j * 8 + 4);
                uint4 u;
                u.x = pack2h(__float2half_rn(v0.x), __float2half_rn(v0.y));
                u.y = pack2h(__float2half_rn(v0.z), __float2half_rn(v0.w));
                u.z = pack2h(__float2half_rn(v1.x), __float2half_rn(v1.y));
                u.w = pack2h(__float2half_rn(v1.z), __float2half_rn(v1.w));
                *(uint4*)(stc + A_OFF + swz(a_sw_base + j * 16)) = u;
            }
        } else {
            #pragma unroll
            for (int j = 0; j < 4; j++) {
                uint32_t sw = swz(a_sw_base + j * 16);
                CP16(stb + A_OFF + sw, Ar + k0 + j * 8);
            }
        }
        const __half* wh = Wt + (size_t)kc * 8192 + tid * 32;
        #pragma unroll
        for (int j = 0; j < 4; j++)
            CP16(stb + B_OFF + tid * 64 + j * 16, wh + j * 8);
        CP_COMMIT();
    };

    const int wid = tid >> 5;
    const int lane = tid & 31;
    const int wm = (wid & 3) * 32;
    const int wn = (wid >> 2) * 64;

    float acc[2][8][4];
    #pragma unroll
    for (int i = 0; i < 2; i++)
        #pragma unroll
        for (int j = 0; j < 8; j++)
            #pragma unroll
            for (int q = 0; q < 4; q++) acc[i][j][q] = 0.0f;

    const int mat = lane >> 3, rin = lane & 7;
    const int a_row = ((mat & 1) << 3) + rin;
    const int a_kh  = (mat >> 1) << 3;
    const int b_row = ((mat >> 1) << 3) + rin;
    const int b_kh  = (mat & 1) << 3;

    auto consume = [&](int s) {
        const uint32_t aSm = smb + s * STAGE_BYTES + A_OFF;
        const uint32_t bSm = smb + s * STAGE_BYTES + B_OFF;
        #pragma unroll
        for (int k16 = 0; k16 < KC / 16; k16++) {
            const int kh = k16 * 16;
            uint32_t ah[2][4], bh[4][4];
            #pragma unroll
            for (int mi = 0; mi < 2; mi++) {
                uint32_t sw = swz((uint32_t)(wm + mi * 16 + a_row) * 128 + (kh + a_kh) * 2);
                LDSM_X4(ah[mi][0], ah[mi][1], ah[mi][2], ah[mi][3], aSm + sw);
            }
            #pragma unroll
            for (int nf = 0; nf < 4; nf++) {
                uint32_t sw = swz((uint32_t)(wn + nf * 16 + b_row) * 128 + (kh + b_kh) * 2);
                LDSM_X4(bh[nf][0], bh[nf][1], bh[nf][2], bh[nf][3], bSm + sw);
            }
            #pragma unroll
            for (int mi = 0; mi < 2; mi++)
                #pragma unroll
                for (int nf = 0; nf < 4; nf++)
                    #pragma unroll
                    for (int nn = 0; nn < 2; nn++)
                        mma_fp16(acc[mi][nf * 2 + nn], ah[mi],
                                 bh[nf][nn * 2], bh[nf][nn * 2 + 1]);
        }
    };

    issue(0); issue(1);
    for (int kc = 0; kc < NK; kc++) {
        if (kc + 2 < NK) { CP_WAIT1(); } else { CP_WAIT0(); }
        __syncthreads();
        if (kc + 2 < NK) issue(kc + 2);
        consume(kc % NSTAGE);
    }

    __half* Oh;
    if (DST == 0)      Oh = g_h1;
    else if (DST == 1) Oh = g_h2;
    else               Oh = g_a1;

    const int qrow = lane >> 2;
    const int qcol = (lane & 3) * 2;
    #pragma unroll
    for (int mi = 0; mi < 2; mi++) {
        #pragma unroll
        for (int half = 0; half < 2; half++) {
            const int m = m0 + wm + mi * 16 + qrow + half * 8;
            if (MODE != 0 && m >= mend) continue;
            #pragma unroll
            for (int nj = 0; nj < 8; nj++) {
                const int col = n0 + wn + nj * 8 + qcol;
                float v0 = acc[mi][nj][half * 2 + 0] + __ldg(bc + col);
                float v1 = acc[mi][nj][half * 2 + 1] + __ldg(bc + col + 1);
                v0 = fmaxf(v0, 0.0f); v1 = fmaxf(v1, 0.0f);
                *(uint32_t*)(Oh + (size_t)m * N + col) =
                    pack2h(__float2half_rn(v0), __float2half_rn(v1));
            }
        }
    }
}

// ---------------- fused head L2 GEMM + L3 dot + sigmoid + scatter -------------
__global__ __launch_bounds__(HTHREADS, 1)
void gemm_head(const float* __restrict__ Hb2,
               const float* __restrict__ HW3,
               const float* __restrict__ Hb3,
               float* __restrict__ out)
{
    extern __shared__ __align__(1024) char smem[];
    __shared__ float part[128][4];
    constexpr int K = 512, N = 256, NK = K / KC;
    const int tid = threadIdx.x;
    const int c = blockIdx.z;

    const int mstart = g_off[c], mend = g_off[c + 1];
    const int m0 = mstart + blockIdx.y * 128;
    if (m0 >= mend) return;

    const float* bc = Hb2 + (size_t)c * N;
    const float* w3 = HW3 + (size_t)c * N;
    const uint32_t smb = smem_u32(smem);

    const int ar = tid >> 2;
    const int aq = tid & 3;
    int apos = m0 + ar;
    if (apos > mend - 1) apos = mend - 1;
    const __half* Ar = g_a1 + (size_t)apos * K + aq * 16;
    const uint32_t a_sw_base = (uint32_t)ar * 128 + aq * 32;

    const int wid = tid >> 5;
    const int lane = tid & 31;
    const int wm = (wid & 3) * 32;
    const int wn = (wid >> 2) * 64;

    float acc[2][8][4];
    #pragma unroll
    for (int i = 0; i < 2; i++)
        #pragma unroll
        for (int j = 0; j < 8; j++)
            #pragma unroll
            for (int q = 0; q < 4; q++) acc[i][j][q] = 0.0f;

    const int mat = lane >> 3, rin = lane & 7;
    const int a_row = ((mat & 1) << 3) + rin;
    const int a_kh  = (mat >> 1) << 3;
    const int b_row = ((mat >> 1) << 3) + rin;
    const int b_kh  = (mat & 1) << 3;

    auto consume = [&](int s) {
        const uint32_t aSm = smb + s * HSTAGE_BYTES + A_OFF;
        const uint32_t bSm = smb + s * HSTAGE_BYTES + B_OFF;
        #pragma unroll
        for (int k16 = 0; k16 < KC / 16; k16++) {
            const int kh = k16 * 16;
            uint32_t ah[2][4], bh[4][4];
            #pragma unroll
            for (int mi = 0; mi < 2; mi++) {
                uint32_t sw = swz((uint32_t)(wm + mi * 16 + a_row) * 128 + (kh + a_kh) * 2);
                LDSM_X4(ah[mi][0], ah[mi][1], ah[mi][2], ah[mi][3], aSm + sw);
            }
            #pragma unroll
            for (int nf = 0; nf < 4; nf++) {
                const int colb = wn + nf * 16;
                uint32_t base = bSm + (colb >> 7) * 16384;
                uint32_t sw = swz((uint32_t)((colb & 127) + b_row) * 128 + (kh + b_kh) * 2);
                LDSM_X4(bh[nf][0], bh[nf][1], bh[nf][2], bh[nf][3], base + sw);
            }
            #pragma unroll
            for (int mi = 0; mi < 2; mi++)
                #pragma unroll
                for (int nf = 0; nf < 4; nf++)
                    #pragma unroll
                    for (int nn = 0; nn < 2; nn++)
                        mma_fp16(acc[mi][nf * 2 + nn], ah[mi],
                                 bh[nf][nn * 2], bh[nf][nn * 2 + 1]);
        }
    };

    auto issue2 = [&](int kc) {
        const int s = kc % NSTAGE;
        const uint32_t stb = smb + s * HSTAGE_BYTES;
        const int k0 = kc * KC;
        #pragma unroll
        for (int j = 0; j < 2; j++) {
            uint32_t sw = swz(a_sw_base + j * 16);
            CP16(stb + A_OFF + sw, Ar + k0 + j * 8);
        }
        const int h2 = tid >> 8;
        const int t4 = tid & 255;
        const __half* wh = g_hw2 + ((((size_t)c * 2 + h2) * (K >> 6)) + kc) * 8192 + t4 * 32;
        #pragma unroll
        for (int j = 0; j < 4; j++)
            CP16(stb + B_OFF + h2 * 16384 + t4 * 64 + j * 16, wh + j * 8);
        CP_COMMIT();
    };

    issue2(0); issue2(1);
    for (int kc = 0; kc < NK; kc++) {
        if (kc + 2 < NK) { CP_WAIT1(); } else { CP_WAIT0(); }
        __syncthreads();
        if (kc + 2 < NK) issue2(kc + 2);
        consume(kc % NSTAGE);
    }

    const int qrow = lane >> 2;
    const int qcol = (lane & 3) * 2;
    float psum[2][2];
    #pragma unroll
    for (int mi = 0; mi < 2; mi++)
        #pragma unroll
        for (int half = 0; half < 2; half++) {
            float p = 0.0f;
            #pragma unroll
            for (int nj = 0; nj < 8; nj++) {
                const int col = wn + nj * 8 + qcol;
                float v0 = fmaxf(acc[mi][nj][half * 2 + 0] + __ldg(bc + col), 0.0f);
                float v1 = fmaxf(acc[mi][nj][half * 2 + 1] + __ldg(bc + col + 1), 0.0f);
                p = fmaf(v0, __ldg(w3 + col), p);
                p = fmaf(v1, __ldg(w3 + col + 1), p);
            }
            psum[mi][half] = p;
        }
    #pragma unroll
    for (int mi = 0; mi < 2; mi++)
        #pragma unroll
        for (int half = 0; half < 2; half++) {
            float p = psum[mi][half];
            p += __shfl_xor_sync(0xFFFFFFFFu, p, 1);
            p += __shfl_xor_sync(0xFFFFFFFFu, p, 2);
            psum[mi][half] = p;
        }
    if ((lane & 3) == 0) {
        #pragma unroll
        for (int mi = 0; mi < 2; mi++)
            #pragma unroll
            for (int half = 0; half < 2; half++)
                part[wm + mi * 16 + qrow + half * 8][wid >> 2] = psum[mi][half];
    }
    __syncthreads();
    if (tid < 128) {
        const int m = m0 + tid;
        if (m < mend) {
            float s = part[tid][0] + part[tid][1] + part[tid][2] + part[tid][3]
                    + __ldg(Hb3 + c);
            out[g_rowmap[m]] = 1.0f / (1.0f + expf(-s));
        }
    }
}

// ---------------- launch ----------------
extern "C" void kernel_launch(void* const* d_in, const int* in_sizes, int n_in,
                              void* d_out, int out_size)
{
    const float* x     = (const float*)d_in[0];
    const int*   flags = (const int*)  d_in[1];
    const float* W1    = (const float*)d_in[2];
    const float* b1    = (const float*)d_in[3];
    const float* W2    = (const float*)d_in[4];
    const float* b2    = (const float*)d_in[5];
    const float* HW1   = (const float*)d_in[6];
    const float* Hb1   = (const float*)d_in[7];
    const float* HW2   = (const float*)d_in[8];
    const float* Hb2   = (const float*)d_in[9];
    const float* HW3   = (const float*)d_in[10];
    const float* Hb3   = (const float*)d_in[11];
    float* out = (float*)d_out;

    cudaFuncSetAttribute(gemm_mma<0, 0, 0, 0, 256, 1024>,
                         cudaFuncAttributeMaxDynamicSharedMemorySize, GEMM_SMEM);
    cudaFuncSetAttribute(gemm_mma<0, 1, 1, 1, 1024, 1024>,
                         cudaFuncAttributeMaxDynamicSharedMemorySize, GEMM_SMEM);
    cudaFuncSetAttribute(gemm_mma<1, 2, 2, 2, 1024, 512>,
                         cudaFuncAttributeMaxDynamicSharedMemorySize, GEMM_SMEM);
    cudaFuncSetAttribute(gemm_head,
                         cudaFuncAttributeMaxDynamicSharedMemorySize, HGEMM_SMEM);

    // fork: side stream does partition + HW1/HW2/W2 conversion, overlapping gemm1
    cudaEventRecord(g_gs.fork, 0);
    cudaStreamWaitEvent(g_gs.side, g_gs.fork, 0);
    prep_side_k<<<449, 1024, 0, g_gs.side>>>(flags, HW1, HW2, W2);
    cudaEventRecord(g_gs.join, g_gs.side);

    // main stream: W1 conversion only, then trunk gemm1 (x converted inline)
    prep_main_k<<<32, 1024>>>(W1);
    // trunk L1: [16384,256] @ [256,1024] -> h1 (A = fp32 x, converted in loader)
    gemm_mma<0, 0, 0, 0, 256, 1024><<<dim3(8, 128, 1), GTHREADS, GEMM_SMEM>>>(b1, x);

    // join: gemm2 needs W2; gemm3 needs rowmap + hw1; head needs hw2
    cudaStreamWaitEvent(0, g_gs.join, 0);
    // trunk L2: [16384,1024] @ [1024,1024] -> h2
    gemm_mma<0, 1, 1, 1, 1024, 1024><<<dim3(8, 128, 1), GTHREADS, GEMM_SMEM>>>(b2, nullptr);
    // head L1 (gather per-combo): [cnt_c,1024] @ HW1[c][1024,512] -> a1
    gemm_mma<1, 2, 2, 2, 1024, 512><<<dim3(4, 128, 4), GTHREADS, GEMM_SMEM>>>(Hb1, nullptr);
    // head L2+L3 fused: [cnt_c,512] @ HW2[c] -> relu -> dot HW3[c] -> sigmoid -> out
    gemm_head<<<dim3(1, 128, 4), HTHREADS, HGEMM_SMEM>>>(Hb2, HW3, Hb3, out);
}

// round 16
// speedup vs baseline: 1.0788x; 1.0788x over previous
#include <cuda_runtime.h>
#include <cuda_fp16.h>
#include <math.h>
#include <stdint.h>

#define BATCH 16384
#define KC 64                       // K elements per SMEM stage
#define STAGE_BYTES 32768           // A 16KB + B 16KB
#define A_OFF 0
#define B_OFF 16384
#define NSTAGE 3
#define GEMM_SMEM (NSTAGE * STAGE_BYTES)
#define GTHREADS 256
// fused head kernel: CTA 128x256, A 16KB + B 32KB
#define HSTAGE_BYTES 49152
#define HGEMM_SMEM (NSTAGE * HSTAGE_BYTES)
#define HTHREADS 512

// ---------------- scratch (no allocations allowed) ----------------
__device__ __half g_x[BATCH * 256];
__device__ __half g_h1[BATCH * 1024];
__device__ __half g_h2[BATCH * 1024];
__device__ __half g_a1[BATCH * 512];
// weights: fp16, transposed to K-major + pre-swizzled blocked tiles
// blocked layout: [c][nt=N/128][kt=K/64][8192 elems]
__device__ __half g_w1[256 * 1024];
__device__ __half g_w2[1024 * 1024];
__device__ __half g_hw1[4 * 1024 * 512];
__device__ __half g_hw2[4 * 512 * 256];
__device__ int g_rowmap[BATCH];
__device__ int g_off[5];

// ---------------- static streams/events for graph fork-join -------------------
struct _GraphStreams {
    cudaStream_t side;
    cudaEvent_t fork, joinW2, join;
    _GraphStreams() {
        cudaStreamCreateWithFlags(&side, cudaStreamNonBlocking);
        cudaEventCreateWithFlags(&fork, cudaEventDisableTiming);
        cudaEventCreateWithFlags(&joinW2, cudaEventDisableTiming);
        cudaEventCreateWithFlags(&join, cudaEventDisableTiming);
    }
};
static _GraphStreams g_gs;

// ---------------- helpers (baseline PTX only) ----------------
__device__ __forceinline__ uint32_t smem_u32(const void* p) {
    uint32_t a;
    asm("{ .reg .u64 t; cvta.to.shared.u64 t, %1; cvt.u32.u64 %0, t; }" : "=r"(a) : "l"(p));
    return a;
}
#define LDSM_X4(r0, r1, r2, r3, addr) \
    asm volatile("ldmatrix.sync.aligned.m8n8.x4.shared.b16 {%0,%1,%2,%3}, [%4];" \
                 : "=r"(r0), "=r"(r1), "=r"(r2), "=r"(r3) : "r"(addr))
#define CP16(dst, src) \
    asm volatile("cp.async.cg.shared.global [%0], [%1], 16;" :: "r"(dst), "l"(src) : "memory")
#define CP_COMMIT() asm volatile("cp.async.commit_group;" ::: "memory")
#define CP_WAIT1() asm volatile("cp.async.wait_group 1;" ::: "memory")
#define CP_WAIT0() asm volatile("cp.async.wait_group 0;" ::: "memory")

__device__ __forceinline__ void mma_fp16(float* d, const uint32_t* a, uint32_t b0, uint32_t b1) {
    asm volatile(
        "mma.sync.aligned.m16n8k16.row.col.f32.f16.f16.f32 "
        "{%0,%1,%2,%3}, {%4,%5,%6,%7}, {%8,%9}, {%0,%1,%2,%3};"
        : "+f"(d[0]), "+f"(d[1]), "+f"(d[2]), "+f"(d[3])
        : "r"(a[0]), "r"(a[1]), "r"(a[2]), "r"(a[3]), "r"(b0), "r"(b1));
}
__device__ __forceinline__ uint32_t pack2h(__half a, __half b) {
    return ((uint32_t)__half_as_ushort(b) << 16) | (uint32_t)__half_as_ushort(a);
}
__device__ __forceinline__ uint32_t swz(uint32_t off) { return off ^ ((off >> 3) & 0x70); }

// ---------------- splitW worker: one 8-deep k-column of one weight matrix -----
__device__ __forceinline__ void splitW_item(const float* __restrict__ src, __half* __restrict__ dh,
                                            int K, int N, int idx) {
    const int kg = K >> 3;
    const int n_ = idx % N;
    const int t  = idx / N;
    const int k8 = (t % kg) * 8;
    const int c  = t / kg;

    const float* s = src + ((size_t)c * K + k8) * N + n_;
    __half hb[8];
    #pragma unroll
    for (int j = 0; j < 8; j++) hb[j] = __float2half_rn(s[(size_t)j * N]);

    const int nt = n_ >> 7, rr = n_ & 127, kt = k8 >> 6, kk = k8 & 63;
    const size_t base = (((size_t)c * (N >> 7) + nt) * (K >> 6) + kt) * 8192;
    const uint32_t sw = swz((uint32_t)rr * 128 + kk * 2);
    *(uint4*)((char*)(dh + base) + sw) = *(uint4*)hb;
}

// ---------------- main-stream prep: splitX + convert W1 -----------------------
// blocks [0,1024): splitX (4 floats/thread); [1024,1056): W1 (32768 items)
__global__ void prep_main_k(const float* __restrict__ x, const float* __restrict__ W1) {
    const int b = blockIdx.x;
    const int tid = threadIdx.x;
    if (b < 1024) {
        int idx = b * 1024 + tid;
        float4 v = *(const float4*)(x + (size_t)idx * 4);
        *(uint2*)(g_x + (size_t)idx * 4) =
            make_uint2(pack2h(__float2half_rn(v.x), __float2half_rn(v.y)),
                       pack2h(__float2half_rn(v.z), __float2half_rn(v.w)));
    } else {
        int widx = (b - 1024) * 1024 + tid;
        if (widx < 32768) splitW_item(W1, g_w1, 256, 1024, widx);
    }
}

// ---------------- side-stream prep #1: convert W2 (joins before gemm2) --------
__global__ void prep_w2_k(const float* __restrict__ W2) {
    int idx = blockIdx.x * 1024 + threadIdx.x;
    if (idx < 131072) splitW_item(W2, g_w2, 1024, 1024, idx);
}

// ---------------- side-stream prep #2: partition + HW1/HW2 (joins before gemm3)
// block 0: partition; blocks [1,321): HW1 (262144) then HW2 (65536)
__global__ void prep_side_k(const int* __restrict__ flags,
                            const float* __restrict__ HW1, const float* __restrict__ HW2) {
    const int b = blockIdx.x;
    const int tid = threadIdx.x;
    if (b == 0) {
        __shared__ int soff[4];
        const int lane = tid & 31;
        if (tid < 4) soff[tid] = 0;
        __syncthreads();
        for (int i = tid; i < BATCH; i += 1024) {
            int c = flags[2 * i] * 2 + flags[2 * i + 1];
            unsigned same = __match_any_sync(0xFFFFFFFFu, c);
            int leader = __ffs(same) - 1;
            if (lane == leader) atomicAdd(&soff[c], __popc(same));
        }
        __syncthreads();
        if (tid == 0) {
            int o = 0;
            #pragma unroll
            for (int c = 0; c < 4; c++) { int n = soff[c]; g_off[c] = o; soff[c] = o; o += n; }
            g_off[4] = o;
        }
        __syncthreads();
        for (int i = tid; i < BATCH; i += 1024) {
            int c = flags[2 * i] * 2 + flags[2 * i + 1];
            unsigned same = __match_any_sync(0xFFFFFFFFu, c);
            int leader = __ffs(same) - 1;
            int rank = __popc(same & ((1u << lane) - 1u));
            int base = 0;
            if (lane == leader) base = atomicAdd(&soff[c], __popc(same));
            base = __shfl_sync(0xFFFFFFFFu, base, leader);
            g_rowmap[base + rank] = i;
        }
    } else {
        int widx = (b - 1) * 1024 + tid;
        if (widx < 262144)      splitW_item(HW1, g_hw1, 1024, 512, widx);
        else if (widx < 327680) splitW_item(HW2, g_hw2, 512, 256, widx - 262144);
    }
}

// ---------------- warp-MMA fp16 GEMM + bias + relu (256 thr, 2 CTA/SM) --------
// CTA tile 128x128, 8 warps in 4(m) x 2(n) grid, warp tile 32x64.
// MODE: 0 dense, 1 gather via g_rowmap
// ASRC: 0 g_x, 1 g_h1, 2 g_h2 / WSRC: 0 w1, 1 w2, 2 hw1 / DST: 0 g_h1, 1 g_h2, 2 g_a1
template <int MODE, int ASRC, int WSRC, int DST, int K, int N>
__global__ __launch_bounds__(GTHREADS, 2)
void gemm_mma(const float* __restrict__ Bias)
{
    extern __shared__ __align__(1024) char smem[];
    constexpr int NK = K / KC;
    const int tid = threadIdx.x;
    const int c = blockIdx.z;

    int mstart, mend;
    if (MODE == 0) { mstart = 0; mend = BATCH; }
    else           { mstart = g_off[c]; mend = g_off[c + 1]; }
    const int m0 = mstart + blockIdx.y * 128;
    if (m0 >= mend) return;
    const int n0 = blockIdx.x * 128;

    const float* bc = Bias + (size_t)c * N;
    const uint32_t smb = smem_u32(smem);

    const __half* Ab;
    if (ASRC == 0)      Ab = g_x;
    else if (ASRC == 1) Ab = g_h1;
    else                Ab = g_h2;
    const __half* Wb;
    if (WSRC == 0)      Wb = g_w1;
    else if (WSRC == 1) Wb = g_w2;
    else                Wb = g_hw1;
    const __half* Wt = Wb + (((size_t)c * (N >> 7) + blockIdx.x) * (K >> 6)) * 8192;

    const int ar = tid >> 1;
    const int aqe = (tid & 1) * 32;
    int apos = m0 + ar;
    if (apos > mend - 1) apos = mend - 1;
    const int grow = (MODE == 1) ? g_rowmap[apos] : apos;
    const __half* Ar = Ab + (size_t)grow * K + aqe;
    const uint32_t a_sw_base = (uint32_t)ar * 128 + aqe * 2;

    auto issue = [&](int kc) {
        const int s = kc % NSTAGE;
        const uint32_t stb = smb + s * STAGE_BYTES;
        const int k0 = kc * KC;
        #pragma unroll
        for (int j = 0; j < 4; j++) {
            uint32_t sw = swz(a_sw_base + j * 16);
            CP16(stb + A_OFF + sw, Ar + k0 + j * 8);
        }
        const __half* wh = Wt + (size_t)kc * 8192 + tid * 32;
        #pragma unroll
        for (int j = 0; j < 4; j++)
            CP16(stb + B_OFF + tid * 64 + j * 16, wh + j * 8);
        CP_COMMIT();
    };

    const int wid = tid >> 5;
    const int lane = tid & 31;
    const int wm = (wid & 3) * 32;
    const int wn = (wid >> 2) * 64;

    float acc[2][8][4];
    #pragma unroll
    for (int i = 0; i < 2; i++)
        #pragma unroll
        for (int j = 0; j < 8; j++)
            #pragma unroll
            for (int q = 0; q < 4; q++) acc[i][j][q] = 0.0f;

    const int mat = lane >> 3, rin = lane & 7;
    const int a_row = ((mat & 1) << 3) + rin;
    const int a_kh  = (mat >> 1) << 3;
    const int b_row = ((mat >> 1) << 3) + rin;
    const int b_kh  = (mat & 1) << 3;

    auto consume = [&](int s) {
        const uint32_t aSm = smb + s * STAGE_BYTES + A_OFF;
        const uint32_t bSm = smb + s * STAGE_BYTES + B_OFF;
        #pragma unroll
        for (int k16 = 0; k16 < KC / 16; k16++) {
            const int kh = k16 * 16;
            uint32_t ah[2][4], bh[4][4];
            #pragma unroll
            for (int mi = 0; mi < 2; mi++) {
                uint32_t sw = swz((uint32_t)(wm + mi * 16 + a_row) * 128 + (kh + a_kh) * 2);
                LDSM_X4(ah[mi][0], ah[mi][1], ah[mi][2], ah[mi][3], aSm + sw);
            }
            #pragma unroll
            for (int nf = 0; nf < 4; nf++) {
                uint32_t sw = swz((uint32_t)(wn + nf * 16 + b_row) * 128 + (kh + b_kh) * 2);
                LDSM_X4(bh[nf][0], bh[nf][1], bh[nf][2], bh[nf][3], bSm + sw);
            }
            #pragma unroll
            for (int mi = 0; mi < 2; mi++)
                #pragma unroll
                for (int nf = 0; nf < 4; nf++)
                    #pragma unroll
                    for (int nn = 0; nn < 2; nn++)
                        mma_fp16(acc[mi][nf * 2 + nn], ah[mi],
                                 bh[nf][nn * 2], bh[nf][nn * 2 + 1]);
        }
    };

    issue(0); issue(1);
    for (int kc = 0; kc < NK; kc++) {
        if (kc + 2 < NK) { CP_WAIT1(); } else { CP_WAIT0(); }
        __syncthreads();
        if (kc + 2 < NK) issue(kc + 2);
        consume(kc % NSTAGE);
    }

    __half* Oh;
    if (DST == 0)      Oh = g_h1;
    else if (DST == 1) Oh = g_h2;
    else               Oh = g_a1;

    const int qrow = lane >> 2;
    const int qcol = (lane & 3) * 2;
    #pragma unroll
    for (int mi = 0; mi < 2; mi++) {
        #pragma unroll
        for (int half = 0; half < 2; half++) {
            const int m = m0 + wm + mi * 16 + qrow + half * 8;
            if (MODE != 0 && m >= mend) continue;
            #pragma unroll
            for (int nj = 0; nj < 8; nj++) {
                const int col = n0 + wn + nj * 8 + qcol;
                float v0 = acc[mi][nj][half * 2 + 0] + __ldg(bc + col);
                float v1 = acc[mi][nj][half * 2 + 1] + __ldg(bc + col + 1);
                v0 = fmaxf(v0, 0.0f); v1 = fmaxf(v1, 0.0f);
                *(uint32_t*)(Oh + (size_t)m * N + col) =
                    pack2h(__float2half_rn(v0), __float2half_rn(v1));
            }
        }
    }
}

// ---------------- fused head L2 GEMM + L3 dot + sigmoid + scatter -------------
__global__ __launch_bounds__(HTHREADS, 1)
void gemm_head(const float* __restrict__ Hb2,
               const float* __restrict__ HW3,
               const float* __restrict__ Hb3,
               float* __restrict__ out)
{
    extern __shared__ __align__(1024) char smem[];
    __shared__ float part[128][4];
    constexpr int K = 512, N = 256, NK = K / KC;
    const int tid = threadIdx.x;
    const int c = blockIdx.z;

    const int mstart = g_off[c], mend = g_off[c + 1];
    const int m0 = mstart + blockIdx.y * 128;
    if (m0 >= mend) return;

    const float* bc = Hb2 + (size_t)c * N;
    const float* w3 = HW3 + (size_t)c * N;
    const uint32_t smb = smem_u32(smem);

    const int ar = tid >> 2;
    const int aq = tid & 3;
    int apos = m0 + ar;
    if (apos > mend - 1) apos = mend - 1;
    const __half* Ar = g_a1 + (size_t)apos * K + aq * 16;
    const uint32_t a_sw_base = (uint32_t)ar * 128 + aq * 32;

    const int wid = tid >> 5;
    const int lane = tid & 31;
    const int wm = (wid & 3) * 32;
    const int wn = (wid >> 2) * 64;

    float acc[2][8][4];
    #pragma unroll
    for (int i = 0; i < 2; i++)
        #pragma unroll
        for (int j = 0; j < 8; j++)
            #pragma unroll
            for (int q = 0; q < 4; q++) acc[i][j][q] = 0.0f;

    const int mat = lane >> 3, rin = lane & 7;
    const int a_row = ((mat & 1) << 3) + rin;
    const int a_kh  = (mat >> 1) << 3;
    const int b_row = ((mat >> 1) << 3) + rin;
    const int b_kh  = (mat & 1) << 3;

    auto consume = [&](int s) {
        const uint32_t aSm = smb + s * HSTAGE_BYTES + A_OFF;
        const uint32_t bSm = smb + s * HSTAGE_BYTES + B_OFF;
        #pragma unroll
        for (int k16 = 0; k16 < KC / 16; k16++) {
            const int kh = k16 * 16;
            uint32_t ah[2][4], bh[4][4];
            #pragma unroll
            for (int mi = 0; mi < 2; mi++) {
                uint32_t sw = swz((uint32_t)(wm + mi * 16 + a_row) * 128 + (kh + a_kh) * 2);
                LDSM_X4(ah[mi][0], ah[mi][1], ah[mi][2], ah[mi][3], aSm + sw);
            }
            #pragma unroll
            for (int nf = 0; nf < 4; nf++) {
                const int colb = wn + nf * 16;
                uint32_t base = bSm + (colb >> 7) * 16384;
                uint32_t sw = swz((uint32_t)((colb & 127) + b_row) * 128 + (kh + b_kh) * 2);
                LDSM_X4(bh[nf][0], bh[nf][1], bh[nf][2], bh[nf][3], base + sw);
            }
            #pragma unroll
            for (int mi = 0; mi < 2; mi++)
                #pragma unroll
                for (int nf = 0; nf < 4; nf++)
                    #pragma unroll
                    for (int nn = 0; nn < 2; nn++)
                        mma_fp16(acc[mi][nf * 2 + nn], ah[mi],
                                 bh[nf][nn * 2], bh[nf][nn * 2 + 1]);
        }
    };

    auto issue2 = [&](int kc) {
        const int s = kc % NSTAGE;
        const uint32_t stb = smb + s * HSTAGE_BYTES;
        const int k0 = kc * KC;
        #pragma unroll
        for (int j = 0; j < 2; j++) {
            uint32_t sw = swz(a_sw_base + j * 16);
            CP16(stb + A_OFF + sw, Ar + k0 + j * 8);
        }
        const int h2 = tid >> 8;
        const int t4 = tid & 255;
        const __half* wh = g_hw2 + ((((size_t)c * 2 + h2) * (K >> 6)) + kc) * 8192 + t4 * 32;
        #pragma unroll
        for (int j = 0; j < 4; j++)
            CP16(stb + B_OFF + h2 * 16384 + t4 * 64 + j * 16, wh + j * 8);
        CP_COMMIT();
    };

    issue2(0); issue2(1);
    for (int kc = 0; kc < NK; kc++) {
        if (kc + 2 < NK) { CP_WAIT1(); } else { CP_WAIT0(); }
        __syncthreads();
        if (kc + 2 < NK) issue2(kc + 2);
        consume(kc % NSTAGE);
    }

    const int qrow = lane >> 2;
    const int qcol = (lane & 3) * 2;
    float psum[2][2];
    #pragma unroll
    for (int mi = 0; mi < 2; mi++)
        #pragma unroll
        for (int half = 0; half < 2; half++) {
            float p = 0.0f;
            #pragma unroll
            for (int nj = 0; nj < 8; nj++) {
                const int col = wn + nj * 8 + qcol;
                float v0 = fmaxf(acc[mi][nj][half * 2 + 0] + __ldg(bc + col), 0.0f);
                float v1 = fmaxf(acc[mi][nj][half * 2 + 1] + __ldg(bc + col + 1), 0.0f);
                p = fmaf(v0, __ldg(w3 + col), p);
                p = fmaf(v1, __ldg(w3 + col + 1), p);
            }
            psum[mi][half] = p;
        }
    #pragma unroll
    for (int mi = 0; mi < 2; mi++)
        #pragma unroll
        for (int half = 0; half < 2; half++) {
            float p = psum[mi][half];
            p += __shfl_xor_sync(0xFFFFFFFFu, p, 1);
            p += __shfl_xor_sync(0xFFFFFFFFu, p, 2);
            psum[mi][half] = p;
        }
    if ((lane & 3) == 0) {
        #pragma unroll
        for (int mi = 0; mi < 2; mi++)
            #pragma unroll
            for (int half = 0; half < 2; half++)
                part[wm + mi * 16 + qrow + half * 8][wid >> 2] = psum[mi][half];
    }
    __syncthreads();
    if (tid < 128) {
        const int m = m0 + tid;
        if (m < mend) {
            float s = part[tid][0] + part[tid][1] + part[tid][2] + part[tid][3]
                    + __ldg(Hb3 + c);
            out[g_rowmap[m]] = 1.0f / (1.0f + expf(-s));
        }
    }
}

// ---------------- launch ----------------
extern "C" void kernel_launch(void* const* d_in, const int* in_sizes, int n_in,
                              void* d_out, int out_size)
{
    const float* x     = (const float*)d_in[0];
    const int*   flags = (const int*)  d_in[1];
    const float* W1    = (const float*)d_in[2];
    const float* b1    = (const float*)d_in[3];
    const float* W2    = (const float*)d_in[4];
    const float* b2    = (const float*)d_in[5];
    const float* HW1   = (const float*)d_in[6];
    const float* Hb1   = (const float*)d_in[7];
    const float* HW2   = (const float*)d_in[8];
    const float* Hb2   = (const float*)d_in[9];
    const float* HW3   = (const float*)d_in[10];
    const float* Hb3   = (const float*)d_in[11];
    float* out = (float*)d_out;

    cudaFuncSetAttribute(gemm_mma<0, 0, 0, 0, 256, 1024>,
                         cudaFuncAttributeMaxDynamicSharedMemorySize, GEMM_SMEM);
    cudaFuncSetAttribute(gemm_mma<0, 1, 1, 1, 1024, 1024>,
                         cudaFuncAttributeMaxDynamicSharedMemorySize, GEMM_SMEM);
    cudaFuncSetAttribute(gemm_mma<1, 2, 2, 2, 1024, 512>,
                         cudaFuncAttributeMaxDynamicSharedMemorySize, GEMM_SMEM);
    cudaFuncSetAttribute(gemm_head,
                         cudaFuncAttributeMaxDynamicSharedMemorySize, HGEMM_SMEM);

    // fork: side stream converts W2 first (early join before gemm2),
    // then partition + HW1/HW2 (join before gemm3)
    cudaEventRecord(g_gs.fork, 0);
    cudaStreamWaitEvent(g_gs.side, g_gs.fork, 0);
    prep_w2_k<<<128, 1024, 0, g_gs.side>>>(W2);
    cudaEventRecord(g_gs.joinW2, g_gs.side);
    prep_side_k<<<321, 1024, 0, g_gs.side>>>(flags, HW1, HW2);
    cudaEventRecord(g_gs.join, g_gs.side);

    // main stream: splitX + W1 conversion, then trunk gemm1
    prep_main_k<<<1056, 1024>>>(x, W1);
    // trunk L1: [16384,256] @ [256,1024] -> h1
    gemm_mma<0, 0, 0, 0, 256, 1024><<<dim3(8, 128, 1), GTHREADS, GEMM_SMEM>>>(b1);

    // gemm2 needs W2 (early join)
    cudaStreamWaitEvent(0, g_gs.joinW2, 0);
    // trunk L2: [16384,1024] @ [1024,1024] -> h2
    gemm_mma<0, 1, 1, 1, 1024, 1024><<<dim3(8, 128, 1), GTHREADS, GEMM_SMEM>>>(b2);

    // gemm3 needs rowmap + hw1; head needs hw2 (full join)
    cudaStreamWaitEvent(0, g_gs.join, 0);
    // head L1 (gather per-combo): [cnt_c,1024] @ HW1[c][1024,512] -> a1
    gemm_mma<1, 2, 2, 2, 1024, 512><<<dim3(4, 128, 4), GTHREADS, GEMM_SMEM>>>(Hb1);
    // head L2+L3 fused: [cnt_c,512] @ HW2[c] -> relu -> dot HW3[c] -> sigmoid -> out
    gemm_head<<<dim3(1, 128, 4), HTHREADS, HGEMM_SMEM>>>(Hb2, HW3, Hb3, out);
}

// round 17
// speedup vs baseline: 1.0962x; 1.0161x over previous
#include <cuda_runtime.h>
#include <cuda_fp16.h>
#include <math.h>
#include <stdint.h>

#define BATCH 16384
#define KC 64                       // K elements per SMEM stage
#define STAGE_BYTES 32768           // A 16KB + B 16KB
#define A_OFF 0
#define B_OFF 16384
#define NSTAGE 3
#define GEMM_SMEM (NSTAGE * STAGE_BYTES)
#define GTHREADS 256
// fused head kernel: CTA 128x256, A 16KB + B 32KB
#define HSTAGE_BYTES 49152
#define HGEMM_SMEM (NSTAGE * HSTAGE_BYTES)
#define HTHREADS 512

// ---------------- scratch (no allocations allowed) ----------------
__device__ __half g_x[BATCH * 256];
__device__ __half g_h1[BATCH * 1024];
__device__ __half g_h2[BATCH * 1024];
__device__ __half g_a1[BATCH * 512];
// weights: fp16, transposed to K-major + pre-swizzled blocked tiles
// blocked layout: [c][nt=N/128][kt=K/64][8192 elems]
__device__ __half g_w1[256 * 1024];
__device__ __half g_w2[1024 * 1024];
__device__ __half g_hw1[4 * 1024 * 512];
__device__ __half g_hw2[4 * 512 * 256];
__device__ int g_rowmap[BATCH];
__device__ int g_off[5];

// ---------------- static streams/events for graph fork-join -------------------
struct _GraphStreams {
    cudaStream_t side;
    cudaEvent_t fork, join;
    _GraphStreams() {
        cudaStreamCreateWithFlags(&side, cudaStreamNonBlocking);
        cudaEventCreateWithFlags(&fork, cudaEventDisableTiming);
        cudaEventCreateWithFlags(&join, cudaEventDisableTiming);
    }
};
static _GraphStreams g_gs;

// ---------------- helpers (baseline PTX only; griddepcontrol is sm_90+ base) --
__device__ __forceinline__ uint32_t smem_u32(const void* p) {
    uint32_t a;
    asm("{ .reg .u64 t; cvta.to.shared.u64 t, %1; cvt.u32.u64 %0, t; }" : "=r"(a) : "l"(p));
    return a;
}
#define LDSM_X4(r0, r1, r2, r3, addr) \
    asm volatile("ldmatrix.sync.aligned.m8n8.x4.shared.b16 {%0,%1,%2,%3}, [%4];" \
                 : "=r"(r0), "=r"(r1), "=r"(r2), "=r"(r3) : "r"(addr))
#define CP16(dst, src) \
    asm volatile("cp.async.cg.shared.global [%0], [%1], 16;" :: "r"(dst), "l"(src) : "memory")
#define CP_COMMIT() asm volatile("cp.async.commit_group;" ::: "memory")
#define CP_WAIT1() asm volatile("cp.async.wait_group 1;" ::: "memory")
#define CP_WAIT0() asm volatile("cp.async.wait_group 0;" ::: "memory")
#define PDL_WAIT() asm volatile("griddepcontrol.wait;" ::: "memory")
#define PDL_TRIGGER() asm volatile("griddepcontrol.launch_dependents;")

__device__ __forceinline__ void mma_fp16(float* d, const uint32_t* a, uint32_t b0, uint32_t b1) {
    asm volatile(
        "mma.sync.aligned.m16n8k16.row.col.f32.f16.f16.f32 "
        "{%0,%1,%2,%3}, {%4,%5,%6,%7}, {%8,%9}, {%0,%1,%2,%3};"
        : "+f"(d[0]), "+f"(d[1]), "+f"(d[2]), "+f"(d[3])
        : "r"(a[0]), "r"(a[1]), "r"(a[2]), "r"(a[3]), "r"(b0), "r"(b1));
}
__device__ __forceinline__ uint32_t pack2h(__half a, __half b) {
    return ((uint32_t)__half_as_ushort(b) << 16) | (uint32_t)__half_as_ushort(a);
}
__device__ __forceinline__ uint32_t swz(uint32_t off) { return off ^ ((off >> 3) & 0x70); }

// ---------------- splitW worker: one 8-deep k-column of one weight matrix -----
__device__ __forceinline__ void splitW_item(const float* __restrict__ src, __half* __restrict__ dh,
                                            int K, int N, int idx) {
    const int kg = K >> 3;
    const int n_ = idx % N;
    const int t  = idx / N;
    const int k8 = (t % kg) * 8;
    const int c  = t / kg;

    const float* s = src + ((size_t)c * K + k8) * N + n_;
    __half hb[8];
    #pragma unroll
    for (int j = 0; j < 8; j++) hb[j] = __float2half_rn(s[(size_t)j * N]);

    const int nt = n_ >> 7, rr = n_ & 127, kt = k8 >> 6, kk = k8 & 63;
    const size_t base = (((size_t)c * (N >> 7) + nt) * (K >> 6) + kt) * 8192;
    const uint32_t sw = swz((uint32_t)rr * 128 + kk * 2);
    *(uint4*)((char*)(dh + base) + sw) = *(uint4*)hb;
}

// ---------------- main-stream prep: splitX + convert W1/W2 --------------------
// blocks [0,1024): splitX; [1024,1184): W1 (32768 items) then W2 (131072)
__global__ void prep_main_k(const float* __restrict__ x,
                            const float* __restrict__ W1, const float* __restrict__ W2) {
    const int b = blockIdx.x;
    const int tid = threadIdx.x;
    if (b < 1024) {
        int idx = b * 1024 + tid;
        float4 v = *(const float4*)(x + (size_t)idx * 4);
        *(uint2*)(g_x + (size_t)idx * 4) =
            make_uint2(pack2h(__float2half_rn(v.x), __float2half_rn(v.y)),
                       pack2h(__float2half_rn(v.z), __float2half_rn(v.w)));
    } else {
        int widx = (b - 1024) * 1024 + tid;
        if (widx < 32768)       splitW_item(W1, g_w1, 256, 1024, widx);
        else if (widx < 163840) splitW_item(W2, g_w2, 1024, 1024, widx - 32768);
    }
    PDL_TRIGGER();
}

// ---------------- side-stream prep: partition + convert HW1/HW2 ---------------
__global__ void prep_side_k(const int* __restrict__ flags,
                            const float* __restrict__ HW1, const float* __restrict__ HW2) {
    const int b = blockIdx.x;
    const int tid = threadIdx.x;
    if (b == 0) {
        __shared__ int soff[4];
        const int lane = tid & 31;
        if (tid < 4) soff[tid] = 0;
        __syncthreads();
        for (int i = tid; i < BATCH; i += 1024) {
            int c = flags[2 * i] * 2 + flags[2 * i + 1];
            unsigned same = __match_any_sync(0xFFFFFFFFu, c);
            int leader = __ffs(same) - 1;
            if (lane == leader) atomicAdd(&soff[c], __popc(same));
        }
        __syncthreads();
        if (tid == 0) {
            int o = 0;
            #pragma unroll
            for (int c = 0; c < 4; c++) { int n = soff[c]; g_off[c] = o; soff[c] = o; o += n; }
            g_off[4] = o;
        }
        __syncthreads();
        for (int i = tid; i < BATCH; i += 1024) {
            int c = flags[2 * i] * 2 + flags[2 * i + 1];
            unsigned same = __match_any_sync(0xFFFFFFFFu, c);
            int leader = __ffs(same) - 1;
            int rank = __popc(same & ((1u << lane) - 1u));
            int base = 0;
            if (lane == leader) base = atomicAdd(&soff[c], __popc(same));
            base = __shfl_sync(0xFFFFFFFFu, base, leader);
            g_rowmap[base + rank] = i;
        }
    } else {
        int widx = (b - 1) * 1024 + tid;
        if (widx < 262144)      splitW_item(HW1, g_hw1, 1024, 512, widx);
        else if (widx < 327680) splitW_item(HW2, g_hw2, 512, 256, widx - 262144);
    }
}

// ---------------- warp-MMA fp16 GEMM + bias + relu (256 thr, 2 CTA/SM) --------
// CTA tile 128x128, 8 warps in 4(m) x 2(n) grid, warp tile 32x64.
// MODE: 0 dense, 1 gather via g_rowmap
// ASRC: 0 g_x, 1 g_h1, 2 g_h2 / WSRC: 0 w1, 1 w2, 2 hw1 / DST: 0 g_h1, 1 g_h2, 2 g_a1
// PDL : 1 = wait at top (A and B are producer outputs), 2 = B-prefetch then wait
template <int MODE, int ASRC, int WSRC, int DST, int K, int N, int PDL>
__global__ __launch_bounds__(GTHREADS, 2)
void gemm_mma(const float* __restrict__ Bias)
{
    extern __shared__ __align__(1024) char smem[];
    constexpr int NK = K / KC;
    const int tid = threadIdx.x;
    const int c = blockIdx.z;

    int mstart, mend;
    if (MODE == 0) { mstart = 0; mend = BATCH; }
    else           { mstart = g_off[c]; mend = g_off[c + 1]; }
    const int m0 = mstart + blockIdx.y * 128;
    if (m0 >= mend) return;
    const int n0 = blockIdx.x * 128;

    const float* bc = Bias + (size_t)c * N;
    const uint32_t smb = smem_u32(smem);

    const __half* Ab;
    if (ASRC == 0)      Ab = g_x;
    else if (ASRC == 1) Ab = g_h1;
    else                Ab = g_h2;
    const __half* Wb;
    if (WSRC == 0)      Wb = g_w1;
    else if (WSRC == 1) Wb = g_w2;
    else                Wb = g_hw1;
    const __half* Wt = Wb + (((size_t)c * (N >> 7) + blockIdx.x) * (K >> 6)) * 8192;

    const int ar = tid >> 1;
    const int aqe = (tid & 1) * 32;
    int apos = m0 + ar;
    if (apos > mend - 1) apos = mend - 1;
    const int grow = (MODE == 1) ? g_rowmap[apos] : apos;
    const __half* Ar = Ab + (size_t)grow * K + aqe;
    const uint32_t a_sw_base = (uint32_t)ar * 128 + aqe * 2;

    auto issueA = [&](int kc) {
        const uint32_t stb = smb + (kc % NSTAGE) * STAGE_BYTES;
        const int k0 = kc * KC;
        #pragma unroll
        for (int j = 0; j < 4; j++) {
            uint32_t sw = swz(a_sw_base + j * 16);
            CP16(stb + A_OFF + sw, Ar + k0 + j * 8);
        }
    };
    auto issueB = [&](int kc) {
        const uint32_t stb = smb + (kc % NSTAGE) * STAGE_BYTES;
        const __half* wh = Wt + (size_t)kc * 8192 + tid * 32;
        #pragma unroll
        for (int j = 0; j < 4; j++)
            CP16(stb + B_OFF + tid * 64 + j * 16, wh + j * 8);
    };
    auto issue = [&](int kc) { issueA(kc); issueB(kc); CP_COMMIT(); };

    const int wid = tid >> 5;
    const int lane = tid & 31;
    const int wm = (wid & 3) * 32;
    const int wn = (wid >> 2) * 64;

    float acc[2][8][4];
    #pragma unroll
    for (int i = 0; i < 2; i++)
        #pragma unroll
        for (int j = 0; j < 8; j++)
            #pragma unroll
            for (int q = 0; q < 4; q++) acc[i][j][q] = 0.0f;

    const int mat = lane >> 3, rin = lane & 7;
    const int a_row = ((mat & 1) << 3) + rin;
    const int a_kh  = (mat >> 1) << 3;
    const int b_row = ((mat >> 1) << 3) + rin;
    const int b_kh  = (mat & 1) << 3;

    auto consume = [&](int s) {
        const uint32_t aSm = smb + s * STAGE_BYTES + A_OFF;
        const uint32_t bSm = smb + s * STAGE_BYTES + B_OFF;
        #pragma unroll
        for (int k16 = 0; k16 < KC / 16; k16++) {
            const int kh = k16 * 16;
            uint32_t ah[2][4], bh[4][4];
            #pragma unroll
            for (int mi = 0; mi < 2; mi++) {
                uint32_t sw = swz((uint32_t)(wm + mi * 16 + a_row) * 128 + (kh + a_kh) * 2);
                LDSM_X4(ah[mi][0], ah[mi][1], ah[mi][2], ah[mi][3], aSm + sw);
            }
            #pragma unroll
            for (int nf = 0; nf < 4; nf++) {
                uint32_t sw = swz((uint32_t)(wn + nf * 16 + b_row) * 128 + (kh + b_kh) * 2);
                LDSM_X4(bh[nf][0], bh[nf][1], bh[nf][2], bh[nf][3], bSm + sw);
            }
            #pragma unroll
            for (int mi = 0; mi < 2; mi++)
                #pragma unroll
                for (int nf = 0; nf < 4; nf++)
                    #pragma unroll
                    for (int nn = 0; nn < 2; nn++)
                        mma_fp16(acc[mi][nf * 2 + nn], ah[mi],
                                 bh[nf][nn * 2], bh[nf][nn * 2 + 1]);
        }
    };

    // ---- prologue: PDL-aware ----
    if (PDL == 1) {
        PDL_WAIT();                       // A and B both come from predecessor
        issue(0); issue(1);
    } else {
        // B (weights) are NOT produced by the PDL predecessor: prefetch early
        issueB(0); issueB(1); CP_COMMIT();   // group0 = B0+B1
        PDL_WAIT();
        issueA(0); CP_COMMIT();              // group1 = A0
        issueA(1); CP_COMMIT();              // group2 = A1
    }
    for (int kc = 0; kc < NK; kc++) {
        if (kc + 2 < NK) { CP_WAIT1(); } else { CP_WAIT0(); }
        __syncthreads();
        if (kc + 2 < NK) issue(kc + 2);
        consume(kc % NSTAGE);
    }

    __half* Oh;
    if (DST == 0)      Oh = g_h1;
    else if (DST == 1) Oh = g_h2;
    else               Oh = g_a1;

    const int qrow = lane >> 2;
    const int qcol = (lane & 3) * 2;
    #pragma unroll
    for (int mi = 0; mi < 2; mi++) {
        #pragma unroll
        for (int half = 0; half < 2; half++) {
            const int m = m0 + wm + mi * 16 + qrow + half * 8;
            if (MODE != 0 && m >= mend) continue;
            #pragma unroll
            for (int nj = 0; nj < 8; nj++) {
                const int col = n0 + wn + nj * 8 + qcol;
                float v0 = acc[mi][nj][half * 2 + 0] + __ldg(bc + col);
                float v1 = acc[mi][nj][half * 2 + 1] + __ldg(bc + col + 1);
                v0 = fmaxf(v0, 0.0f); v1 = fmaxf(v1, 0.0f);
                *(uint32_t*)(Oh + (size_t)m * N + col) =
                    pack2h(__float2half_rn(v0), __float2half_rn(v1));
            }
        }
    }
    PDL_TRIGGER();
}

// ---------------- fused head L2 GEMM + L3 dot + sigmoid + scatter -------------
__global__ __launch_bounds__(HTHREADS, 1)
void gemm_head(const float* __restrict__ Hb2,
               const float* __restrict__ HW3,
               const float* __restrict__ Hb3,
               float* __restrict__ out)
{
    extern __shared__ __align__(1024) char smem[];
    __shared__ float part[128][4];
    constexpr int K = 512, N = 256, NK = K / KC;
    const int tid = threadIdx.x;
    const int c = blockIdx.z;

    const int mstart = g_off[c], mend = g_off[c + 1];
    const int m0 = mstart + blockIdx.y * 128;
    if (m0 >= mend) return;

    const float* bc = Hb2 + (size_t)c * N;
    const float* w3 = HW3 + (size_t)c * N;
    const uint32_t smb = smem_u32(smem);

    const int ar = tid >> 2;
    const int aq = tid & 3;
    int apos = m0 + ar;
    if (apos > mend - 1) apos = mend - 1;
    const __half* Ar = g_a1 + (size_t)apos * K + aq * 16;
    const uint32_t a_sw_base = (uint32_t)ar * 128 + aq * 32;

    const int wid = tid >> 5;
    const int lane = tid & 31;
    const int wm = (wid & 3) * 32;
    const int wn = (wid >> 2) * 64;

    float acc[2][8][4];
    #pragma unroll
    for (int i = 0; i < 2; i++)
        #pragma unroll
        for (int j = 0; j < 8; j++)
            #pragma unroll
            for (int q = 0; q < 4; q++) acc[i][j][q] = 0.0f;

    const int mat = lane >> 3, rin = lane & 7;
    const int a_row = ((mat & 1) << 3) + rin;
    const int a_kh  = (mat >> 1) << 3;
    const int b_row = ((mat >> 1) << 3) + rin;
    const int b_kh  = (mat & 1) << 3;

    auto consume = [&](int s) {
        const uint32_t aSm = smb + s * HSTAGE_BYTES + A_OFF;
        const uint32_t bSm = smb + s * HSTAGE_BYTES + B_OFF;
        #pragma unroll
        for (int k16 = 0; k16 < KC / 16; k16++) {
            const int kh = k16 * 16;
            uint32_t ah[2][4], bh[4][4];
            #pragma unroll
            for (int mi = 0; mi < 2; mi++) {
                uint32_t sw = swz((uint32_t)(wm + mi * 16 + a_row) * 128 + (kh + a_kh) * 2);
                LDSM_X4(ah[mi][0], ah[mi][1], ah[mi][2], ah[mi][3], aSm + sw);
            }
            #pragma unroll
            for (int nf = 0; nf < 4; nf++) {
                const int colb = wn + nf * 16;
                uint32_t base = bSm + (colb >> 7) * 16384;
                uint32_t sw = swz((uint32_t)((colb & 127) + b_row) * 128 + (kh + b_kh) * 2);
                LDSM_X4(bh[nf][0], bh[nf][1], bh[nf][2], bh[nf][3], base + sw);
            }
            #pragma unroll
            for (int mi = 0; mi < 2; mi++)
                #pragma unroll
                for (int nf = 0; nf < 4; nf++)
                    #pragma unroll
                    for (int nn = 0; nn < 2; nn++)
                        mma_fp16(acc[mi][nf * 2 + nn], ah[mi],
                                 bh[nf][nn * 2], bh[nf][nn * 2 + 1]);
        }
    };

    auto issueA2 = [&](int kc) {
        const uint32_t stb = smb + (kc % NSTAGE) * HSTAGE_BYTES;
        const int k0 = kc * KC;
        #pragma unroll
        for (int j = 0; j < 2; j++) {
            uint32_t sw = swz(a_sw_base + j * 16);
            CP16(stb + A_OFF + sw, Ar + k0 + j * 8);
        }
    };
    auto issueB2 = [&](int kc) {
        const uint32_t stb = smb + (kc % NSTAGE) * HSTAGE_BYTES;
        const int h2 = tid >> 8;
        const int t4 = tid & 255;
        const __half* wh = g_hw2 + ((((size_t)c * 2 + h2) * (K >> 6)) + kc) * 8192 + t4 * 32;
        #pragma unroll
        for (int j = 0; j < 4; j++)
            CP16(stb + B_OFF + h2 * 16384 + t4 * 64 + j * 16, wh + j * 8);
    };
    auto issue2 = [&](int kc) { issueA2(kc); issueB2(kc); CP_COMMIT(); };

    // B (g_hw2, side stream) prefetched before PDL wait; A (g_a1) after
    issueB2(0); issueB2(1); CP_COMMIT();
    PDL_WAIT();
    issueA2(0); CP_COMMIT();
    issueA2(1); CP_COMMIT();
    for (int kc = 0; kc < NK; kc++) {
        if (kc + 2 < NK) { CP_WAIT1(); } else { CP_WAIT0(); }
        __syncthreads();
        if (kc + 2 < NK) issue2(kc + 2);
        consume(kc % NSTAGE);
    }

    const int qrow = lane >> 2;
    const int qcol = (lane & 3) * 2;
    float psum[2][2];
    #pragma unroll
    for (int mi = 0; mi < 2; mi++)
        #pragma unroll
        for (int half = 0; half < 2; half++) {
            float p = 0.0f;
            #pragma unroll
            for (int nj = 0; nj < 8; nj++) {
                const int col = wn + nj * 8 + qcol;
                float v0 = fmaxf(acc[mi][nj][half * 2 + 0] + __ldg(bc + col), 0.0f);
                float v1 = fmaxf(acc[mi][nj][half * 2 + 1] + __ldg(bc + col + 1), 0.0f);
                p = fmaf(v0, __ldg(w3 + col), p);
                p = fmaf(v1, __ldg(w3 + col + 1), p);
            }
            psum[mi][half] = p;
        }
    #pragma unroll
    for (int mi = 0; mi < 2; mi++)
        #pragma unroll
        for (int half = 0; half < 2; half++) {
            float p = psum[mi][half];
            p += __shfl_xor_sync(0xFFFFFFFFu, p, 1);
            p += __shfl_xor_sync(0xFFFFFFFFu, p, 2);
            psum[mi][half] = p;
        }
    if ((lane & 3) == 0) {
        #pragma unroll
        for (int mi = 0; mi < 2; mi++)
            #pragma unroll
            for (int half = 0; half < 2; half++)
                part[wm + mi * 16 + qrow + half * 8][wid >> 2] = psum[mi][half];
    }
    __syncthreads();
    if (tid < 128) {
        const int m = m0 + tid;
        if (m < mend) {
            float s = part[tid][0] + part[tid][1] + part[tid][2] + part[tid][3]
                    + __ldg(Hb3 + c);
            out[g_rowmap[m]] = 1.0f / (1.0f + expf(-s));
        }
    }
}

// ---------------- PDL launch helper ----------------
template <typename F, typename... Args>
static inline void launch_pdl(F f, dim3 gr, dim3 bl, size_t sm, Args... args) {
    cudaLaunchConfig_t cfg = {};
    cfg.gridDim = gr; cfg.blockDim = bl; cfg.dynamicSmemBytes = sm; cfg.stream = 0;
    cudaLaunchAttribute attr[1];
    attr[0].id = cudaLaunchAttributeProgrammaticStreamSerialization;
    attr[0].val.programmaticStreamSerializationAllowed = 1;
    cfg.attrs = attr; cfg.numAttrs = 1;
    cudaLaunchKernelEx(&cfg, f, args...);
}

// ---------------- launch ----------------
extern "C" void kernel_launch(void* const* d_in, const int* in_sizes, int n_in,
                              void* d_out, int out_size)
{
    const float* x     = (const float*)d_in[0];
    const int*   flags = (const int*)  d_in[1];
    const float* W1    = (const float*)d_in[2];
    const float* b1    = (const float*)d_in[3];
    const float* W2    = (const float*)d_in[4];
    const float* b2    = (const float*)d_in[5];
    const float* HW1   = (const float*)d_in[6];
    const float* Hb1   = (const float*)d_in[7];
    const float* HW2   = (const float*)d_in[8];
    const float* Hb2   = (const float*)d_in[9];
    const float* HW3   = (const float*)d_in[10];
    const float* Hb3   = (const float*)d_in[11];
    float* out = (float*)d_out;

    cudaFuncSetAttribute(gemm_mma<0, 0, 0, 0, 256, 1024, 1>,
                         cudaFuncAttributeMaxDynamicSharedMemorySize, GEMM_SMEM);
    cudaFuncSetAttribute(gemm_mma<0, 1, 1, 1, 1024, 1024, 2>,
                         cudaFuncAttributeMaxDynamicSharedMemorySize, GEMM_SMEM);
    cudaFuncSetAttribute(gemm_mma<1, 2, 2, 2, 1024, 512, 2>,
                         cudaFuncAttributeMaxDynamicSharedMemorySize, GEMM_SMEM);
    cudaFuncSetAttribute(gemm_head,
                         cudaFuncAttributeMaxDynamicSharedMemorySize, HGEMM_SMEM);

    // fork: side stream does partition + HW1/HW2 conversion, overlapping gemm1/2
    cudaEventRecord(g_gs.fork, 0);
    cudaStreamWaitEvent(g_gs.side, g_gs.fork, 0);
    prep_side_k<<<321, 1024, 0, g_gs.side>>>(flags, HW1, HW2);
    cudaEventRecord(g_gs.join, g_gs.side);

    // main stream: splitX + W1/W2 conversion, then trunk gemms (PDL-chained)
    prep_main_k<<<1184, 1024>>>(x, W1, W2);
    // trunk L1: [16384,256] @ [256,1024] -> h1
    launch_pdl(gemm_mma<0, 0, 0, 0, 256, 1024, 1>,
               dim3(8, 128, 1), dim3(GTHREADS), GEMM_SMEM, b1);
    // trunk L2: [16384,1024] @ [1024,1024] -> h2 (B prefetch pre-wait)
    launch_pdl(gemm_mma<0, 1, 1, 1, 1024, 1024, 2>,
               dim3(8, 128, 1), dim3(GTHREADS), GEMM_SMEM, b2);

    // join: gemm3 needs rowmap + hw1; head needs hw2
    cudaStreamWaitEvent(0, g_gs.join, 0);
    // head L1 (gather per-combo): [cnt_c,1024] @ HW1[c][1024,512] -> a1
    launch_pdl(gemm_mma<1, 2, 2, 2, 1024, 512, 2>,
               dim3(4, 128, 4), dim3(GTHREADS), GEMM_SMEM, Hb1);
    // head L2+L3 fused: [cnt_c,512] @ HW2[c] -> relu -> dot HW3[c] -> sigmoid -> out
    launch_pdl(gemm_head, dim3(1, 128, 4), dim3(HTHREADS), HGEMM_SMEM,
               Hb2, HW3, Hb3, out);
}